// round 9
// baseline (speedup 1.0000x reference)
#include <cuda_runtime.h>
#include <cuda_bf16.h>
#include <cstdint>

#define Sd 2048
#define Bd 256
#define Hd 256
#define Pd 3
#define NCTAS 148
#define ITEMS 16384           // 256 b * 64 s-chunks of 32

__device__ float g_hid2[Bd * Hd];
__device__ float g_attn_part[4 * Bd * Sd];   // per-colgroup energy partials
__device__ float g_ctx_part[8 * Bd * Hd];
__device__ float g_h1[Bd * Hd];
__device__ float g_scale[Hd];
__device__ float g_shift[Hd];

__device__ __forceinline__ float sigmoidf_(float x) {
    return 1.0f / (1.0f + __expf(-x));
}
__device__ __forceinline__ float tanh_ap(float x) {
    float y; asm("tanh.approx.f32 %0, %1;" : "=f"(y) : "f"(x)); return y;
}
__device__ __forceinline__ uint32_t smem_u32f(const void* p) {
    uint32_t a;
    asm("{ .reg .u64 t; cvta.to.shared.u64 t, %1; cvt.u32.u64 %0, t; }" : "=r"(a) : "l"(p));
    return a;
}
__device__ __forceinline__ void ldsm_x4(uint32_t& r0, uint32_t& r1,
                                        uint32_t& r2, uint32_t& r3, uint32_t addr) {
    asm volatile("ldmatrix.sync.aligned.m8n8.x4.shared.b16 {%0,%1,%2,%3}, [%4];"
                 : "=r"(r0), "=r"(r1), "=r"(r2), "=r"(r3) : "r"(addr));
}
__device__ __forceinline__ void mma16816(float* d, uint32_t a0, uint32_t a1,
                                         uint32_t a2, uint32_t a3,
                                         uint32_t b0, uint32_t b1) {
    asm volatile(
        "mma.sync.aligned.m16n8k16.row.col.f32.bf16.bf16.f32 "
        "{%0,%1,%2,%3},{%4,%5,%6,%7},{%8,%9},{%0,%1,%2,%3};"
        : "+f"(d[0]), "+f"(d[1]), "+f"(d[2]), "+f"(d[3])
        : "r"(a0), "r"(a1), "r"(a2), "r"(a3), "r"(b0), "r"(b1));
}

// hid2[b,k] = 0.5*(ldh@Wh^T + bh + be)  (pre-scaled for tanh form)
__global__ void hid2_kernel(const float* __restrict__ ldh, const float* __restrict__ Wh,
                            const float* __restrict__ bh, const float* __restrict__ be) {
    int b = blockIdx.x, tid = threadIdx.x, lane = tid & 31, warp = tid >> 5;
    __shared__ float hsm[Hd];
    hsm[tid] = ldh[b * Hd + tid];
    __syncthreads();
    for (int k = warp; k < Hd; k += 8) {
        float a = 0.f;
        #pragma unroll
        for (int t = 0; t < 8; t++) a += hsm[lane + 32 * t] * Wh[k * Hd + lane + 32 * t];
        #pragma unroll
        for (int o = 16; o; o >>= 1) a += __shfl_xor_sync(0xffffffffu, a, o);
        if (lane == 0) g_hid2[b * Hd + k] = 0.5f * (a + bh[k] + be[k]);
    }
}

// ---------------- persistent HMMA energy kernel, fp32 register ingest -----
// part[cg][b][s] = sum_{c in cg*64..+63} wv2[c]*tanh(0.5*(X@We^T)[m,c]+hid2[b,c])
#define WST 264
#define OFF_WE 0
#define SZ_WE (256 * WST * 2)               // 135168
#define OFF_X0 SZ_WE                        // 135168
#define SZ_XB (32 * WST * 2)                // 16896
#define OFF_X1 (OFF_X0 + SZ_XB)             // 152064
#define OFF_WV (OFF_X1 + SZ_XB)             // 168960
#define ESMEM (OFF_WV + 1024)               // 169984

__global__ __launch_bounds__(256, 1)
void energy_hmma_kernel(const float* __restrict__ X, const float* __restrict__ We,
                        const float* __restrict__ Wv) {
    extern __shared__ char smem[];
    const uint32_t sm32 = smem_u32f(smem);
    const int tid = threadIdx.x, lane = tid & 31, wid = tid >> 5;
    float* wv2s = (float*)(smem + OFF_WV);

    // stage We (row n = tid) as bf16 [n][k] stride 264, once
    {
        const float2* wr = (const float2*)(We + tid * Hd);
        __nv_bfloat16* wd = (__nv_bfloat16*)(smem + OFF_WE) + tid * WST;
        #pragma unroll 8
        for (int j = 0; j < 128; j++) {
            float2 v = wr[j];
            __nv_bfloat162 p = __floats2bfloat162_rn(v.x, v.y);
            *(uint32_t*)(wd + 2 * j) = *(uint32_t*)&p;
        }
    }
    wv2s[tid] = 0.5f * Wv[tid];

    const int start = (ITEMS * blockIdx.x) / NCTAS;
    const int n = (ITEMS * (blockIdx.x + 1)) / NCTAS - start;
    const int row_t = tid >> 3, seg_t = tid & 7;   // staging: row, 128B segment

    // load item i's fp32 region into registers (8 x float4 per thread)
    auto load_regs = [&](int i, float4* f) {
        int item = start + i;
        int bb = item >> 6, s0 = (item & 63) << 5;
        const float4* src = (const float4*)(X + ((size_t)(s0 + row_t) * Bd + bb) * Hd
                                            + seg_t * 32);
        #pragma unroll
        for (int j = 0; j < 8; j++) f[j] = src[j];
    };
    // convert registers -> bf16 tile buf
    auto convert = [&](int buf, const float4* f) {
        __nv_bfloat16* xd = (__nv_bfloat16*)(smem + (buf ? OFF_X1 : OFF_X0))
                          + row_t * WST + seg_t * 32;
        #pragma unroll
        for (int v = 0; v < 4; v++) {
            float4 f0 = f[2 * v], f1 = f[2 * v + 1];
            __nv_bfloat162 q0 = __floats2bfloat162_rn(f0.x, f0.y);
            __nv_bfloat162 q1 = __floats2bfloat162_rn(f0.z, f0.w);
            __nv_bfloat162 q2 = __floats2bfloat162_rn(f1.x, f1.y);
            __nv_bfloat162 q3 = __floats2bfloat162_rn(f1.z, f1.w);
            uint4 u = { *(uint32_t*)&q0, *(uint32_t*)&q1,
                        *(uint32_t*)&q2, *(uint32_t*)&q3 };
            *(uint4*)(xd + v * 8) = u;
        }
    };

    // prologue: item 0 into buf 0
    {
        float4 f[8];
        load_regs(0, f);
        convert(0, f);
    }
    __syncthreads();   // We, wv2, xb[0] visible

    const int rg = wid & 1, cg = wid >> 1;
    const int r0 = rg * 16, c0 = cg * 64;
    const uint32_t a_rel = (uint32_t)((r0 + (lane & 15)) * WST + (lane >> 4) * 8) * 2;
    const uint32_t b_base = sm32 + OFF_WE
        + (uint32_t)((c0 + (lane & 7) + ((lane >> 4) << 3)) * WST + ((lane >> 3) & 1) * 8) * 2;

    for (int i = 0; i < n; i++) {
        const int item = start + i;
        const int bb = item >> 6, s0 = (item & 63) << 5;

        // issue next item's global loads now; consumed after MMA+epilogue
        float4 f[8];
        if (i + 1 < n) load_regs(i + 1, f);

        // MMA: 16 rows x 64 cols x k256 per warp, reading xb[i&1]
        float d[8][4];
        #pragma unroll
        for (int nt = 0; nt < 8; nt++)
            #pragma unroll
            for (int j = 0; j < 4; j++) d[nt][j] = 0.f;

        const uint32_t abase = sm32 + ((i & 1) ? OFF_X1 : OFF_X0) + a_rel;
        #pragma unroll 4
        for (int ks = 0; ks < 16; ks++) {
            uint32_t a0, a1, a2, a3;
            ldsm_x4(a0, a1, a2, a3, abase + ks * 32);
            #pragma unroll
            for (int np = 0; np < 4; np++) {
                uint32_t b0, b1, b2, b3;
                ldsm_x4(b0, b1, b2, b3, b_base + (uint32_t)(np * 16 * WST) * 2 + ks * 32);
                mma16816(d[2 * np],     a0, a1, a2, a3, b0, b1);
                mma16816(d[2 * np + 1], a0, a1, a2, a3, b2, b3);
            }
        }

        // epilogue: tanh + Wv dot, per-warp 64-col partial -> g_attn_part[cg]
        {
            const float* h2 = g_hid2 + bb * Hd;
            float p0 = 0.f, p1 = 0.f;
            #pragma unroll
            for (int nt = 0; nt < 8; nt++) {
                int col = c0 + nt * 8 + (lane & 3) * 2;
                float w0 = wv2s[col], w1 = wv2s[col + 1];
                float h0 = __ldg(h2 + col), h1 = __ldg(h2 + col + 1);
                p0 += w0 * tanh_ap(fmaf(0.5f, d[nt][0], h0))
                    + w1 * tanh_ap(fmaf(0.5f, d[nt][1], h1));
                p1 += w0 * tanh_ap(fmaf(0.5f, d[nt][2], h0))
                    + w1 * tanh_ap(fmaf(0.5f, d[nt][3], h1));
            }
            p0 += __shfl_xor_sync(0xffffffffu, p0, 1);
            p0 += __shfl_xor_sync(0xffffffffu, p0, 2);
            p1 += __shfl_xor_sync(0xffffffffu, p1, 1);
            p1 += __shfl_xor_sync(0xffffffffu, p1, 2);
            if ((lane & 3) == 0) {
                int q = lane >> 2;
                size_t base = (size_t)cg * (Bd * Sd) + (size_t)bb * Sd + s0 + r0 + q;
                g_attn_part[base] = p0;
                g_attn_part[base + 8] = p1;
            }
        }

        // convert next item into the other buffer (safe: all warps finished
        // reading it at the barrier that ended iteration i-1)
        if (i + 1 < n) convert((i + 1) & 1, f);
        __syncthreads();   // xb[(i+1)&1] ready; all warps done with xb[i&1]
    }
}

// ---------------- softmax over s, per b (sums 4 partial slices) -----------
__global__ void softmax_kernel(float* __restrict__ attn) {
    int b = blockIdx.x, tid = threadIdx.x;
    const size_t sl = (size_t)Bd * Sd;
    float* row = attn + b * Sd;
    float v[8]; float mx = -1e30f;
    #pragma unroll
    for (int t = 0; t < 8; t++) {
        size_t idx = (size_t)b * Sd + tid + 256 * t;
        v[t] = g_attn_part[idx] + g_attn_part[sl + idx]
             + g_attn_part[2 * sl + idx] + g_attn_part[3 * sl + idx];
        mx = fmaxf(mx, v[t]);
    }
    __shared__ float redm[8]; __shared__ float reds[8];
    #pragma unroll
    for (int o = 16; o; o >>= 1) mx = fmaxf(mx, __shfl_xor_sync(0xffffffffu, mx, o));
    if ((tid & 31) == 0) redm[tid >> 5] = mx;
    __syncthreads();
    mx = redm[0];
    #pragma unroll
    for (int i = 1; i < 8; i++) mx = fmaxf(mx, redm[i]);
    float sum = 0.f;
    #pragma unroll
    for (int t = 0; t < 8; t++) { v[t] = __expf(v[t] - mx); sum += v[t]; }
    #pragma unroll
    for (int o = 16; o; o >>= 1) sum += __shfl_xor_sync(0xffffffffu, sum, o);
    if ((tid & 31) == 0) reds[tid >> 5] = sum;
    __syncthreads();
    sum = 0.f;
    #pragma unroll
    for (int i = 0; i < 8; i++) sum += reds[i];
    float inv = 1.f / sum;
    #pragma unroll
    for (int t = 0; t < 8; t++) row[tid + 256 * t] = v[t] * inv;
}

// ---------------- context partials: stream fp32 encoder_outputs -----------
__global__ void ctx_part_kernel(const float* __restrict__ enc,
                                const float* __restrict__ attn) {
    int b = blockIdx.x, sc = blockIdx.y, h = threadIdx.x;
    int s0 = sc * 256;
    const float* wrow = attn + b * Sd + s0;
    const float* e = enc + ((size_t)s0 * Bd + b) * Hd + h;
    float a0 = 0.f, a1 = 0.f, a2 = 0.f, a3 = 0.f;
    #pragma unroll 2
    for (int s = 0; s < 256; s += 4) {
        a0 += wrow[s + 0] * e[(size_t)(s + 0) * (Bd * Hd)];
        a1 += wrow[s + 1] * e[(size_t)(s + 1) * (Bd * Hd)];
        a2 += wrow[s + 2] * e[(size_t)(s + 2) * (Bd * Hd)];
        a3 += wrow[s + 3] * e[(size_t)(s + 3) * (Bd * Hd)];
    }
    g_ctx_part[(sc * Bd + b) * Hd + h] = (a0 + a1) + (a2 + a3);
}

__global__ void ctx_reduce_kernel(float* __restrict__ out_ctx) {
    int b = blockIdx.x, h = threadIdx.x;
    float acc = 0.f;
    #pragma unroll
    for (int sc = 0; sc < 8; sc++) acc += g_ctx_part[(sc * Bd + b) * Hd + h];
    out_ctx[b * Hd + h] = acc;
}

// ---------------- GRU -------------------------------------------------------
__global__ void gru_kernel(const float* __restrict__ last_palette, const float* __restrict__ ldh,
                           const float* __restrict__ ctx, const float* __restrict__ W_ih,
                           const float* __restrict__ b_ih, const float* __restrict__ W_hh,
                           const float* __restrict__ b_hh, float* __restrict__ out_gru) {
    int b = blockIdx.x, tid = threadIdx.x, lane = tid & 31, warp = tid >> 5;
    __shared__ float xs[262]; __shared__ float hs[Hd];
    __shared__ float gi[3 * Hd]; __shared__ float gh[3 * Hd];
    if (tid < Pd) xs[tid] = last_palette[b * Pd + tid];
    xs[Pd + tid] = ctx[b * Hd + tid];
    hs[tid] = ldh[b * Hd + tid];
    __syncthreads();
    const int KX = Hd + Pd;
    for (int k = warp; k < 3 * Hd; k += 8) {
        float a = 0.f;
        #pragma unroll
        for (int t = 0; t < 8; t++) a += xs[lane + 32 * t] * W_ih[k * KX + lane + 32 * t];
        if (lane < 3) a += xs[256 + lane] * W_ih[k * KX + 256 + lane];
        #pragma unroll
        for (int o = 16; o; o >>= 1) a += __shfl_xor_sync(0xffffffffu, a, o);
        if (lane == 0) gi[k] = a + b_ih[k];
        float c = 0.f;
        #pragma unroll
        for (int t = 0; t < 8; t++) c += hs[lane + 32 * t] * W_hh[k * Hd + lane + 32 * t];
        #pragma unroll
        for (int o = 16; o; o >>= 1) c += __shfl_xor_sync(0xffffffffu, c, o);
        if (lane == 0) gh[k] = c + b_hh[k];
    }
    __syncthreads();
    int k = tid;
    float r = sigmoidf_(gi[k] + gh[k]);
    float z = sigmoidf_(gi[Hd + k] + gh[Hd + k]);
    float nn = tanhf(gi[2 * Hd + k] + r * gh[2 * Hd + k]);
    out_gru[b * Hd + k] = (1.f - z) * nn + z * hs[k];
}

__global__ void h1_kernel(const float* __restrict__ gru, const float* __restrict__ W1,
                          const float* __restrict__ b1) {
    int b = blockIdx.x, tid = threadIdx.x, lane = tid & 31, warp = tid >> 5;
    __shared__ float gs[Hd];
    gs[tid] = gru[b * Hd + tid];
    __syncthreads();
    for (int k = warp; k < Hd; k += 8) {
        float a = 0.f;
        #pragma unroll
        for (int t = 0; t < 8; t++) a += gs[lane + 32 * t] * W1[k * Hd + lane + 32 * t];
        #pragma unroll
        for (int o = 16; o; o >>= 1) a += __shfl_xor_sync(0xffffffffu, a, o);
        if (lane == 0) g_h1[b * Hd + k] = fmaxf(a + b1[k], 0.f);
    }
}

__global__ void bn_kernel(const float* __restrict__ gamma, const float* __restrict__ beta) {
    int k = threadIdx.x;
    float s = 0.f, sq = 0.f;
    for (int b = 0; b < Bd; b++) { float v = g_h1[b * Hd + k]; s += v; sq += v * v; }
    float mu = s * (1.f / Bd);
    float var = sq * (1.f / Bd) - mu * mu;
    float sc = rsqrtf(var + 1e-5f) * gamma[k];
    g_scale[k] = sc; g_shift[k] = beta[k] - mu * sc;
}

__global__ void palette_kernel(const float* __restrict__ W2, const float* __restrict__ b2,
                               float* __restrict__ out_pal) {
    int b = blockIdx.x, lane = threadIdx.x & 31, p = threadIdx.x >> 5;
    if (p >= Pd) return;
    float a = 0.f;
    #pragma unroll
    for (int t = 0; t < 8; t++) {
        int h = lane + 32 * t;
        a += (g_h1[b * Hd + h] * g_scale[h] + g_shift[h]) * W2[p * Hd + h];
    }
    #pragma unroll
    for (int o = 16; o; o >>= 1) a += __shfl_xor_sync(0xffffffffu, a, o);
    if (lane == 0) out_pal[b * Pd + p] = a + b2[p];
}

extern "C" void kernel_launch(void* const* d_in, const int* in_sizes, int n_in,
                              void* d_out, int out_size) {
    const float* last_palette = (const float*)d_in[0];
    const float* ldh          = (const float*)d_in[1];
    const float* enc          = (const float*)d_in[2];
    const float* We           = (const float*)d_in[3];
    const float* be           = (const float*)d_in[4];
    const float* Wh           = (const float*)d_in[5];
    const float* bh           = (const float*)d_in[6];
    const float* Wv           = (const float*)d_in[7];
    const float* W_ih         = (const float*)d_in[9];
    const float* b_ih         = (const float*)d_in[10];
    const float* W_hh         = (const float*)d_in[11];
    const float* b_hh         = (const float*)d_in[12];
    const float* W1           = (const float*)d_in[13];
    const float* b1           = (const float*)d_in[14];
    const float* gamma        = (const float*)d_in[15];
    const float* beta         = (const float*)d_in[16];
    const float* W2           = (const float*)d_in[17];
    const float* b2           = (const float*)d_in[18];

    float* out      = (float*)d_out;
    float* out_pal  = out;
    float* out_ctx  = out + Bd * Pd;
    float* out_gru  = out + Bd * Pd + Bd * Hd;
    float* out_attn = out + Bd * Pd + 2 * Bd * Hd;

    static bool attr_done = false;
    if (!attr_done) {
        cudaFuncSetAttribute(energy_hmma_kernel,
                             cudaFuncAttributeMaxDynamicSharedMemorySize, ESMEM);
        attr_done = true;
    }

    hid2_kernel<<<Bd, 256>>>(ldh, Wh, bh, be);
    energy_hmma_kernel<<<NCTAS, 256, ESMEM>>>(enc, We, Wv);
    softmax_kernel<<<Bd, 256>>>(out_attn);
    ctx_part_kernel<<<dim3(Bd, 8), 256>>>(enc, out_attn);
    ctx_reduce_kernel<<<Bd, 256>>>(out_ctx);
    gru_kernel<<<Bd, 256>>>(last_palette, ldh, out_ctx, W_ih, b_ih, W_hh, b_hh, out_gru);
    h1_kernel<<<Bd, 256>>>(out_gru, W1, b1);
    bn_kernel<<<1, 256>>>(gamma, beta);
    palette_kernel<<<Bd, 128>>>(W2, b2, out_pal);
}

// round 10
// speedup vs baseline: 1.1188x; 1.1188x over previous
#include <cuda_runtime.h>
#include <cuda_bf16.h>
#include <cstdint>

#define Sd 2048
#define Bd 256
#define Hd 256
#define Pd 3
#define NCTAS 148
#define ITEMS 16384           // 256 b * 64 s-chunks of 32

__device__ float g_hid2[Bd * Hd];
__device__ float g_attn_part[8 * Bd * Sd];   // per (half,colgroup) energy partials
__device__ float g_ctx_part[8 * Bd * Hd];
__device__ float g_h1[Bd * Hd];
__device__ float g_scale[Hd];
__device__ float g_shift[Hd];
__device__ float g_gi[Bd * 3 * Hd];
__device__ float g_gh[Bd * 3 * Hd];
__device__ __nv_bfloat16 g_xb[(size_t)Sd * Bd * Hd];   // enc bf16, [b][s][h]

__device__ __forceinline__ float sigmoidf_(float x) {
    return 1.0f / (1.0f + __expf(-x));
}
__device__ __forceinline__ float tanh_ap(float x) {
    float y; asm("tanh.approx.f32 %0, %1;" : "=f"(y) : "f"(x)); return y;
}
__device__ __forceinline__ uint32_t smem_u32f(const void* p) {
    uint32_t a;
    asm("{ .reg .u64 t; cvta.to.shared.u64 t, %1; cvt.u32.u64 %0, t; }" : "=r"(a) : "l"(p));
    return a;
}
__device__ __forceinline__ void ldsm_x4(uint32_t& r0, uint32_t& r1,
                                        uint32_t& r2, uint32_t& r3, uint32_t addr) {
    asm volatile("ldmatrix.sync.aligned.m8n8.x4.shared.b16 {%0,%1,%2,%3}, [%4];"
                 : "=r"(r0), "=r"(r1), "=r"(r2), "=r"(r3) : "r"(addr));
}
__device__ __forceinline__ void mma16816(float* d, uint32_t a0, uint32_t a1,
                                         uint32_t a2, uint32_t a3,
                                         uint32_t b0, uint32_t b1) {
    asm volatile(
        "mma.sync.aligned.m16n8k16.row.col.f32.bf16.bf16.f32 "
        "{%0,%1,%2,%3},{%4,%5,%6,%7},{%8,%9},{%0,%1,%2,%3};"
        : "+f"(d[0]), "+f"(d[1]), "+f"(d[2]), "+f"(d[3])
        : "r"(a0), "r"(a1), "r"(a2), "r"(a3), "r"(b0), "r"(b1));
}
#define CP_ASYNC16(dst, src) \
    asm volatile("cp.async.cg.shared.global [%0], [%1], 16;" :: "r"(dst), "l"(src))
#define CP_COMMIT() asm volatile("cp.async.commit_group;" ::: "memory")
#define CP_WAIT1()  asm volatile("cp.async.wait_group 1;" ::: "memory")

// ---------------- convert: enc fp32 [s][b][h] -> bf16 [b][s][h] -----------
__global__ __launch_bounds__(256)
void convert_kernel(const float* __restrict__ X) {
    int s = blockIdx.x;
    int h8 = (threadIdx.x & 31) * 8;
    int br = threadIdx.x >> 5;
    for (int b = br; b < Bd; b += 8) {
        const float4* src = (const float4*)(X + ((size_t)s * Bd + b) * Hd + h8);
        float4 f0 = src[0], f1 = src[1];
        __nv_bfloat162 q0 = __floats2bfloat162_rn(f0.x, f0.y);
        __nv_bfloat162 q1 = __floats2bfloat162_rn(f0.z, f0.w);
        __nv_bfloat162 q2 = __floats2bfloat162_rn(f1.x, f1.y);
        __nv_bfloat162 q3 = __floats2bfloat162_rn(f1.z, f1.w);
        uint4 u = { *(uint32_t*)&q0, *(uint32_t*)&q1, *(uint32_t*)&q2, *(uint32_t*)&q3 };
        *(uint4*)(g_xb + ((size_t)b * Sd + s) * Hd + h8) = u;
    }
}

// hid2[b,k] = 0.5*(ldh@Wh^T + bh + be)
__global__ void hid2_kernel(const float* __restrict__ ldh, const float* __restrict__ Wh,
                            const float* __restrict__ bh, const float* __restrict__ be) {
    int b = blockIdx.x, tid = threadIdx.x, lane = tid & 31, warp = tid >> 5;
    __shared__ float hsm[Hd];
    hsm[tid] = ldh[b * Hd + tid];
    __syncthreads();
    for (int k = warp; k < Hd; k += 8) {
        float a = 0.f;
        #pragma unroll
        for (int t = 0; t < 8; t++) a += hsm[lane + 32 * t] * Wh[k * Hd + lane + 32 * t];
        #pragma unroll
        for (int o = 16; o; o >>= 1) a += __shfl_xor_sync(0xffffffffu, a, o);
        if (lane == 0) g_hid2[b * Hd + k] = 0.5f * (a + bh[k] + be[k]);
    }
}

// ---------------- energy: 2 CTAs/SM, column-split We ----------------------
// slice = half*4+cg; part[slice][b][s] = sum_{c in 32-col grp} wv2[c]*tanh(...)
#define WST 264
#define OFF_WE 0
#define SZ_WE (128 * WST * 2)               // 67584
#define OFF_X0 SZ_WE                        // 67584
#define SZ_XB (32 * WST * 2)                // 16896
#define OFF_X1 (OFF_X0 + SZ_XB)             // 84480
#define OFF_WV (OFF_X1 + SZ_XB)             // 101376
#define ESMEM (OFF_WV + 512)                // 101888

__global__ __launch_bounds__(256, 2)
void energy_hmma_kernel(const float* __restrict__ We, const float* __restrict__ Wv) {
    extern __shared__ char smem[];
    const uint32_t sm32 = smem_u32f(smem);
    const int tid = threadIdx.x, lane = tid & 31, wid = tid >> 5;
    const int half = blockIdx.x & 1, cta = blockIdx.x >> 1;
    float* wv2s = (float*)(smem + OFF_WV);   // 128 floats

    // stage We rows [half*128, +128) as bf16 [n_local][k] stride 264
    {
        const int n = tid >> 1;                        // 0..127
        const float2* wr = (const float2*)(We + (size_t)(half * 128 + n) * Hd)
                         + (tid & 1) * 64;
        __nv_bfloat16* wd = (__nv_bfloat16*)(smem + OFF_WE) + n * WST + (tid & 1) * 128;
        #pragma unroll 8
        for (int j = 0; j < 64; j++) {
            float2 v = wr[j];
            __nv_bfloat162 p = __floats2bfloat162_rn(v.x, v.y);
            *(uint32_t*)(wd + 2 * j) = *(uint32_t*)&p;
        }
    }
    if (tid < 128) wv2s[tid] = 0.5f * Wv[half * 128 + tid];

    const int start = (ITEMS * cta) / NCTAS;
    const int n = (ITEMS * (cta + 1)) / NCTAS - start;

    // cp.async item i -> buf[i&1]; source 16KB contiguous in g_xb
    auto issue = [&](int i) {
        int item = start + i;
        int bb = item >> 6, s0 = (item & 63) << 5;
        const char* src = (const char*)(g_xb + ((size_t)bb * Sd + s0) * Hd);
        uint32_t dstb = sm32 + ((i & 1) ? OFF_X1 : OFF_X0);
        #pragma unroll
        for (int k = 0; k < 4; k++) {
            int c = tid + k * 256;                 // 1024 chunks of 16B
            uint32_t dst = dstb + (uint32_t)(c >> 5) * (WST * 2) + (uint32_t)(c & 31) * 16;
            CP_ASYNC16(dst, src + (size_t)c * 16);
        }
    };

    issue(0); CP_COMMIT();
    __syncthreads();

    const int rg = wid & 1, cg = wid >> 1;     // rows rg*16, local cols cg*32
    const int r0 = rg * 16, c0 = cg * 32;
    const uint32_t a_rel = (uint32_t)((r0 + (lane & 15)) * WST + (lane >> 4) * 8) * 2;
    const uint32_t b_base = sm32 + OFF_WE
        + (uint32_t)((c0 + (lane & 7) + ((lane >> 4) << 3)) * WST + ((lane >> 3) & 1) * 8) * 2;

    for (int i = 0; i < n; i++) {
        const int item = start + i;
        const int bb = item >> 6, s0 = (item & 63) << 5;

        if (i + 1 < n) issue(i + 1);
        CP_COMMIT();
        CP_WAIT1();
        __syncthreads();   // buf[i&1] filled

        float d[4][4];
        #pragma unroll
        for (int nt = 0; nt < 4; nt++)
            #pragma unroll
            for (int j = 0; j < 4; j++) d[nt][j] = 0.f;

        const uint32_t abase = sm32 + ((i & 1) ? OFF_X1 : OFF_X0) + a_rel;
        #pragma unroll 4
        for (int ks = 0; ks < 16; ks++) {
            uint32_t a0, a1, a2, a3;
            ldsm_x4(a0, a1, a2, a3, abase + ks * 32);
            #pragma unroll
            for (int np = 0; np < 2; np++) {
                uint32_t b0, b1, b2, b3;
                ldsm_x4(b0, b1, b2, b3, b_base + (uint32_t)(np * 16 * WST) * 2 + ks * 32);
                mma16816(d[2 * np],     a0, a1, a2, a3, b0, b1);
                mma16816(d[2 * np + 1], a0, a1, a2, a3, b2, b3);
            }
        }

        // epilogue: tanh + Wv dot over this warp's 32 cols
        {
            const float* h2 = g_hid2 + bb * Hd + half * 128;
            float p0 = 0.f, p1 = 0.f;
            #pragma unroll
            for (int nt = 0; nt < 4; nt++) {
                int c = c0 + nt * 8 + (lane & 3) * 2;       // local col 0..127
                float w0 = wv2s[c], w1 = wv2s[c + 1];
                float h0 = __ldg(h2 + c), h1 = __ldg(h2 + c + 1);
                p0 += w0 * tanh_ap(fmaf(0.5f, d[nt][0], h0))
                    + w1 * tanh_ap(fmaf(0.5f, d[nt][1], h1));
                p1 += w0 * tanh_ap(fmaf(0.5f, d[nt][2], h0))
                    + w1 * tanh_ap(fmaf(0.5f, d[nt][3], h1));
            }
            p0 += __shfl_xor_sync(0xffffffffu, p0, 1);
            p0 += __shfl_xor_sync(0xffffffffu, p0, 2);
            p1 += __shfl_xor_sync(0xffffffffu, p1, 1);
            p1 += __shfl_xor_sync(0xffffffffu, p1, 2);
            if ((lane & 3) == 0) {
                int q = lane >> 2;
                size_t base = (size_t)(half * 4 + cg) * (Bd * Sd)
                            + (size_t)bb * Sd + s0 + r0 + q;
                g_attn_part[base] = p0;
                g_attn_part[base + 8] = p1;
            }
        }
        __syncthreads();   // all warps done reading buf[i&1] before overwrite
    }
}

// ---------------- softmax over s, per b (sums 8 partial slices) -----------
__global__ void softmax_kernel(float* __restrict__ attn) {
    int b = blockIdx.x, tid = threadIdx.x;
    const size_t sl = (size_t)Bd * Sd;
    float* row = attn + b * Sd;
    float v[8]; float mx = -1e30f;
    #pragma unroll
    for (int t = 0; t < 8; t++) {
        size_t idx = (size_t)b * Sd + tid + 256 * t;
        float a = 0.f;
        #pragma unroll
        for (int s8 = 0; s8 < 8; s8++) a += g_attn_part[s8 * sl + idx];
        v[t] = a;
        mx = fmaxf(mx, a);
    }
    __shared__ float redm[8]; __shared__ float reds[8];
    #pragma unroll
    for (int o = 16; o; o >>= 1) mx = fmaxf(mx, __shfl_xor_sync(0xffffffffu, mx, o));
    if ((tid & 31) == 0) redm[tid >> 5] = mx;
    __syncthreads();
    mx = redm[0];
    #pragma unroll
    for (int i = 1; i < 8; i++) mx = fmaxf(mx, redm[i]);
    float sum = 0.f;
    #pragma unroll
    for (int t = 0; t < 8; t++) { v[t] = __expf(v[t] - mx); sum += v[t]; }
    #pragma unroll
    for (int o = 16; o; o >>= 1) sum += __shfl_xor_sync(0xffffffffu, sum, o);
    if ((tid & 31) == 0) reds[tid >> 5] = sum;
    __syncthreads();
    sum = 0.f;
    #pragma unroll
    for (int i = 0; i < 8; i++) sum += reds[i];
    float inv = 1.f / sum;
    #pragma unroll
    for (int t = 0; t < 8; t++) row[tid + 256 * t] = v[t] * inv;
}

// ---------------- context partials: stream fp32 encoder_outputs -----------
__global__ void ctx_part_kernel(const float* __restrict__ enc,
                                const float* __restrict__ attn) {
    int b = blockIdx.x, sc = blockIdx.y, h = threadIdx.x;
    int s0 = sc * 256;
    const float* wrow = attn + b * Sd + s0;
    const float* e = enc + ((size_t)s0 * Bd + b) * Hd + h;
    float a0 = 0.f, a1 = 0.f, a2 = 0.f, a3 = 0.f;
    #pragma unroll 2
    for (int s = 0; s < 256; s += 4) {
        a0 += wrow[s + 0] * e[(size_t)(s + 0) * (Bd * Hd)];
        a1 += wrow[s + 1] * e[(size_t)(s + 1) * (Bd * Hd)];
        a2 += wrow[s + 2] * e[(size_t)(s + 2) * (Bd * Hd)];
        a3 += wrow[s + 3] * e[(size_t)(s + 3) * (Bd * Hd)];
    }
    g_ctx_part[(sc * Bd + b) * Hd + h] = (a0 + a1) + (a2 + a3);
}

__global__ void ctx_reduce_kernel(float* __restrict__ out_ctx) {
    int b = blockIdx.x, h = threadIdx.x;
    float acc = 0.f;
    #pragma unroll
    for (int sc = 0; sc < 8; sc++) acc += g_ctx_part[(sc * Bd + b) * Hd + h];
    out_ctx[b * Hd + h] = acc;
}

// ---------------- GRU: weight-stationary gate GEMM ------------------------
// block k0 = blockIdx*8 gate rows; computes gi[b][k0..k0+7], gh[...] for all b
__global__ __launch_bounds__(256)
void gru_gemm_kernel(const float* __restrict__ last_palette,
                     const float* __restrict__ ldh, const float* __restrict__ ctx,
                     const float* __restrict__ W_ih, const float* __restrict__ W_hh) {
    __shared__ float Wi[8][260];
    __shared__ float Whh[8][256];
    const int tid = threadIdx.x, lane = tid & 31, warp = tid >> 5;
    const int k0 = blockIdx.x * 8;
    const int KX = Hd + Pd;   // 259
    for (int idx = tid; idx < 8 * KX; idx += 256)
        Wi[idx / KX][idx % KX] = W_ih[(size_t)(k0 + idx / KX) * KX + idx % KX];
    for (int idx = tid; idx < 8 * Hd; idx += 256)
        Whh[idx >> 8][idx & 255] = W_hh[(size_t)(k0 + (idx >> 8)) * Hd + (idx & 255)];
    __syncthreads();

    for (int it = 0; it < 32; it++) {
        int b = warp + 8 * it;
        // x[j]: j<3 palette, else ctx[j-3]; lane holds x[lane+32t]
        float xr[8], hr[8];
        #pragma unroll
        for (int t = 0; t < 8; t++) {
            int j = lane + 32 * t;
            xr[t] = (j < 3) ? last_palette[b * Pd + j] : ctx[b * Hd + (j - 3)];
            hr[t] = ldh[b * Hd + j];
        }
        float xe = (lane < 3) ? ctx[b * Hd + 253 + lane] : 0.f;
        #pragma unroll
        for (int o = 0; o < 8; o++) {
            float a = (lane < 3) ? xe * Wi[o][256 + lane] : 0.f;
            float c = 0.f;
            #pragma unroll
            for (int t = 0; t < 8; t++) {
                a += xr[t] * Wi[o][lane + 32 * t];
                c += hr[t] * Whh[o][lane + 32 * t];
            }
            #pragma unroll
            for (int off = 16; off; off >>= 1) {
                a += __shfl_xor_sync(0xffffffffu, a, off);
                c += __shfl_xor_sync(0xffffffffu, c, off);
            }
            if (lane == 0) {
                g_gi[(size_t)b * (3 * Hd) + k0 + o] = a;
                g_gh[(size_t)b * (3 * Hd) + k0 + o] = c;
            }
        }
    }
}

__global__ void gru_combine_kernel(const float* __restrict__ ldh,
                                   const float* __restrict__ b_ih,
                                   const float* __restrict__ b_hh,
                                   float* __restrict__ out_gru) {
    int b = blockIdx.x, k = threadIdx.x;
    const float* gi = g_gi + (size_t)b * (3 * Hd);
    const float* gh = g_gh + (size_t)b * (3 * Hd);
    float r = sigmoidf_(gi[k] + b_ih[k] + gh[k] + b_hh[k]);
    float z = sigmoidf_(gi[Hd + k] + b_ih[Hd + k] + gh[Hd + k] + b_hh[Hd + k]);
    float nn = tanhf(gi[2 * Hd + k] + b_ih[2 * Hd + k]
                     + r * (gh[2 * Hd + k] + b_hh[2 * Hd + k]));
    out_gru[b * Hd + k] = (1.f - z) * nn + z * ldh[b * Hd + k];
}

__global__ void h1_kernel(const float* __restrict__ gru, const float* __restrict__ W1,
                          const float* __restrict__ b1) {
    int b = blockIdx.x, tid = threadIdx.x, lane = tid & 31, warp = tid >> 5;
    __shared__ float gs[Hd];
    gs[tid] = gru[b * Hd + tid];
    __syncthreads();
    for (int k = warp; k < Hd; k += 8) {
        float a = 0.f;
        #pragma unroll
        for (int t = 0; t < 8; t++) a += gs[lane + 32 * t] * W1[k * Hd + lane + 32 * t];
        #pragma unroll
        for (int o = 16; o; o >>= 1) a += __shfl_xor_sync(0xffffffffu, a, o);
        if (lane == 0) g_h1[b * Hd + k] = fmaxf(a + b1[k], 0.f);
    }
}

// ---------------- BatchNorm stats, parallel (16 blocks) --------------------
__global__ void bn_kernel(const float* __restrict__ gamma, const float* __restrict__ beta) {
    __shared__ float ps[16][16];
    __shared__ float pq[16][16];
    int tid = threadIdx.x;
    int kl = tid & 15, bl = tid >> 4;       // k-local, b-lane
    int k = blockIdx.x * 16 + kl;
    float s = 0.f, sq = 0.f;
    #pragma unroll
    for (int j = 0; j < 16; j++) {
        float v = g_h1[(bl + 16 * j) * Hd + k];
        s += v; sq += v * v;
    }
    ps[bl][kl] = s; pq[bl][kl] = sq;
    __syncthreads();
    if (tid < 16) {
        float ts = 0.f, tq = 0.f;
        #pragma unroll
        for (int j = 0; j < 16; j++) { ts += ps[j][tid]; tq += pq[j][tid]; }
        int kk = blockIdx.x * 16 + tid;
        float mu = ts * (1.f / Bd);
        float var = tq * (1.f / Bd) - mu * mu;
        float sc = rsqrtf(var + 1e-5f) * gamma[kk];
        g_scale[kk] = sc; g_shift[kk] = beta[kk] - mu * sc;
    }
}

__global__ void palette_kernel(const float* __restrict__ W2, const float* __restrict__ b2,
                               float* __restrict__ out_pal) {
    int b = blockIdx.x, lane = threadIdx.x & 31, p = threadIdx.x >> 5;
    if (p >= Pd) return;
    float a = 0.f;
    #pragma unroll
    for (int t = 0; t < 8; t++) {
        int h = lane + 32 * t;
        a += (g_h1[b * Hd + h] * g_scale[h] + g_shift[h]) * W2[p * Hd + h];
    }
    #pragma unroll
    for (int o = 16; o; o >>= 1) a += __shfl_xor_sync(0xffffffffu, a, o);
    if (lane == 0) out_pal[b * Pd + p] = a + b2[p];
}

extern "C" void kernel_launch(void* const* d_in, const int* in_sizes, int n_in,
                              void* d_out, int out_size) {
    const float* last_palette = (const float*)d_in[0];
    const float* ldh          = (const float*)d_in[1];
    const float* enc          = (const float*)d_in[2];
    const float* We           = (const float*)d_in[3];
    const float* be           = (const float*)d_in[4];
    const float* Wh           = (const float*)d_in[5];
    const float* bh           = (const float*)d_in[6];
    const float* Wv           = (const float*)d_in[7];
    const float* W_ih         = (const float*)d_in[9];
    const float* b_ih         = (const float*)d_in[10];
    const float* W_hh         = (const float*)d_in[11];
    const float* b_hh         = (const float*)d_in[12];
    const float* W1           = (const float*)d_in[13];
    const float* b1           = (const float*)d_in[14];
    const float* gamma        = (const float*)d_in[15];
    const float* beta         = (const float*)d_in[16];
    const float* W2           = (const float*)d_in[17];
    const float* b2           = (const float*)d_in[18];

    float* out      = (float*)d_out;
    float* out_pal  = out;
    float* out_ctx  = out + Bd * Pd;
    float* out_gru  = out + Bd * Pd + Bd * Hd;
    float* out_attn = out + Bd * Pd + 2 * Bd * Hd;

    static bool attr_done = false;
    if (!attr_done) {
        cudaFuncSetAttribute(energy_hmma_kernel,
                             cudaFuncAttributeMaxDynamicSharedMemorySize, ESMEM);
        attr_done = true;
    }

    convert_kernel<<<Sd, 256>>>(enc);
    hid2_kernel<<<Bd, 256>>>(ldh, Wh, bh, be);
    energy_hmma_kernel<<<2 * NCTAS, 256, ESMEM>>>(We, Wv);
    softmax_kernel<<<Bd, 256>>>(out_attn);
    ctx_part_kernel<<<dim3(Bd, 8), 256>>>(enc, out_attn);
    ctx_reduce_kernel<<<Bd, 256>>>(out_ctx);
    gru_gemm_kernel<<<96, 256>>>(last_palette, ldh, out_ctx, W_ih, W_hh);
    gru_combine_kernel<<<Bd, 256>>>(ldh, b_ih, b_hh, out_gru);
    h1_kernel<<<Bd, 256>>>(out_gru, W1, b1);
    bn_kernel<<<16, 256>>>(gamma, beta);
    palette_kernel<<<Bd, 128>>>(W2, b2, out_pal);
}

// round 11
// speedup vs baseline: 1.2419x; 1.1101x over previous
#include <cuda_runtime.h>
#include <cuda_bf16.h>
#include <cstdint>

#define Sd 2048
#define Bd 256
#define Hd 256
#define Pd 3
#define NCTAS 148
#define ITEMS 8192            // 256 b * 32 s-chunks of 64

__device__ float g_hid2[Bd * Hd];
__device__ float g_attn_part[4 * Bd * Sd];   // per-colgroup energy partials
__device__ float g_ctx_part[8 * Bd * Hd];
__device__ float g_h1[Bd * Hd];
__device__ float g_scale[Hd];
__device__ float g_shift[Hd];
__device__ float g_gi[Bd * 3 * Hd];
__device__ float g_gh[Bd * 3 * Hd];
__device__ __nv_bfloat16 g_xb[(size_t)Sd * Bd * Hd];   // enc bf16, [b][s][h]

__device__ __forceinline__ float sigmoidf_(float x) {
    return 1.0f / (1.0f + __expf(-x));
}
__device__ __forceinline__ float tanh_ap(float x) {
    float y; asm("tanh.approx.f32 %0, %1;" : "=f"(y) : "f"(x)); return y;
}
__device__ __forceinline__ uint32_t smem_u32f(const void* p) {
    uint32_t a;
    asm("{ .reg .u64 t; cvta.to.shared.u64 t, %1; cvt.u32.u64 %0, t; }" : "=r"(a) : "l"(p));
    return a;
}
__device__ __forceinline__ void ldsm_x4(uint32_t& r0, uint32_t& r1,
                                        uint32_t& r2, uint32_t& r3, uint32_t addr) {
    asm volatile("ldmatrix.sync.aligned.m8n8.x4.shared.b16 {%0,%1,%2,%3}, [%4];"
                 : "=r"(r0), "=r"(r1), "=r"(r2), "=r"(r3) : "r"(addr));
}
__device__ __forceinline__ void mma16816(float* d, uint32_t a0, uint32_t a1,
                                         uint32_t a2, uint32_t a3,
                                         uint32_t b0, uint32_t b1) {
    asm volatile(
        "mma.sync.aligned.m16n8k16.row.col.f32.bf16.bf16.f32 "
        "{%0,%1,%2,%3},{%4,%5,%6,%7},{%8,%9},{%0,%1,%2,%3};"
        : "+f"(d[0]), "+f"(d[1]), "+f"(d[2]), "+f"(d[3])
        : "r"(a0), "r"(a1), "r"(a2), "r"(a3), "r"(b0), "r"(b1));
}
#define CP_ASYNC16(dst, src) \
    asm volatile("cp.async.cg.shared.global [%0], [%1], 16;" :: "r"(dst), "l"(src))
#define CP_COMMIT() asm volatile("cp.async.commit_group;" ::: "memory")
#define CP_WAIT1()  asm volatile("cp.async.wait_group 1;" ::: "memory")

// ---------------- convert: enc fp32 [s][b][h] -> bf16 [b][s][h] -----------
__global__ __launch_bounds__(256)
void convert_kernel(const float* __restrict__ X) {
    int s = blockIdx.x;
    int h8 = (threadIdx.x & 31) * 8;
    int br = threadIdx.x >> 5;
    for (int b = br; b < Bd; b += 8) {
        const float4* src = (const float4*)(X + ((size_t)s * Bd + b) * Hd + h8);
        float4 f0 = src[0], f1 = src[1];
        __nv_bfloat162 q0 = __floats2bfloat162_rn(f0.x, f0.y);
        __nv_bfloat162 q1 = __floats2bfloat162_rn(f0.z, f0.w);
        __nv_bfloat162 q2 = __floats2bfloat162_rn(f1.x, f1.y);
        __nv_bfloat162 q3 = __floats2bfloat162_rn(f1.z, f1.w);
        uint4 u = { *(uint32_t*)&q0, *(uint32_t*)&q1, *(uint32_t*)&q2, *(uint32_t*)&q3 };
        *(uint4*)(g_xb + ((size_t)b * Sd + s) * Hd + h8) = u;
    }
}

// hid2[b,k] = 0.5*(ldh@Wh^T + bh + be)
__global__ void hid2_kernel(const float* __restrict__ ldh, const float* __restrict__ Wh,
                            const float* __restrict__ bh, const float* __restrict__ be) {
    int b = blockIdx.x, tid = threadIdx.x, lane = tid & 31, warp = tid >> 5;
    __shared__ float hsm[Hd];
    hsm[tid] = ldh[b * Hd + tid];
    __syncthreads();
    for (int k = warp; k < Hd; k += 8) {
        float a = 0.f;
        #pragma unroll
        for (int t = 0; t < 8; t++) a += hsm[lane + 32 * t] * Wh[k * Hd + lane + 32 * t];
        #pragma unroll
        for (int o = 16; o; o >>= 1) a += __shfl_xor_sync(0xffffffffu, a, o);
        if (lane == 0) g_hid2[b * Hd + k] = 0.5f * (a + bh[k] + be[k]);
    }
}

// ---------------- persistent HMMA energy kernel (cp.async pipeline) -------
// part[cg][b][s] = sum_{c in cg*64..+63} wv2[c]*tanh(0.5*(X@We^T)[m,c]+hid2[b,c])
#define WST 264
#define OFF_WE 0
#define SZ_WE (256 * WST * 2)                // 135168
#define OFF_X0 SZ_WE
#define SZ_X (64 * WST * 2)                  // 33792
#define OFF_X1 (OFF_X0 + SZ_X)
#define OFF_WV (OFF_X1 + SZ_X)               // 202752
#define ESMEM (OFF_WV + 1024)                // 203776

__global__ __launch_bounds__(256, 1)
void energy_hmma_kernel(const float* __restrict__ We,
                        const float* __restrict__ Wv) {
    extern __shared__ char smem[];
    const uint32_t sm32 = smem_u32f(smem);
    const int tid = threadIdx.x, lane = tid & 31, wid = tid >> 5;
    float* wv2s = (float*)(smem + OFF_WV);

    // stage We (row n = tid) as bf16 [n][k] stride 264, once
    {
        const float2* wr = (const float2*)(We + tid * Hd);
        __nv_bfloat16* wd = (__nv_bfloat16*)(smem + OFF_WE) + tid * WST;
        #pragma unroll 8
        for (int j = 0; j < 128; j++) {
            float2 v = wr[j];
            __nv_bfloat162 p = __floats2bfloat162_rn(v.x, v.y);
            *(uint32_t*)(wd + 2 * j) = *(uint32_t*)&p;
        }
    }
    wv2s[tid] = 0.5f * Wv[tid];

    const int start = (ITEMS * blockIdx.x) / NCTAS;
    const int n = (ITEMS * (blockIdx.x + 1)) / NCTAS - start;

    // cp.async issue: item i -> buf[i&1]; source is contiguous 32KB in g_xb
    auto issue = [&](int i) {
        int item = start + i;
        int bb = item >> 5, s0 = (item & 31) << 6;
        const char* src = (const char*)(g_xb + ((size_t)bb * Sd + s0) * Hd);
        uint32_t dstb = sm32 + ((i & 1) ? OFF_X1 : OFF_X0);
        #pragma unroll
        for (int k = 0; k < 8; k++) {
            int c = tid + k * 256;                 // chunk id: row=c>>5, j=c&31
            uint32_t dst = dstb + (uint32_t)(c >> 5) * (WST * 2) + (uint32_t)(c & 31) * 16;
            CP_ASYNC16(dst, src + (size_t)c * 16);
        }
    };

    issue(0); CP_COMMIT();
    __syncthreads();   // We + wv2 visible

    const int rg = wid & 1, cg = wid >> 1;
    const int r0 = rg * 32, c0 = cg * 64;
    const uint32_t a_rel = (uint32_t)((r0 + (lane & 15)) * WST + (lane >> 4) * 8) * 2;
    const uint32_t b_base = sm32 + OFF_WE
        + (uint32_t)((c0 + (lane & 7) + ((lane >> 4) << 3)) * WST + ((lane >> 3) & 1) * 8) * 2;

    for (int i = 0; i < n; i++) {
        const int item = start + i;
        const int bb = item >> 5, s0 = (item & 31) << 6;

        if (i + 1 < n) issue(i + 1);     // buf[(i+1)&1] freed at end of iter i-1
        CP_COMMIT();
        CP_WAIT1();
        __syncthreads();   // buf[i&1] filled, visible to all warps

        const uint32_t xb = sm32 + ((i & 1) ? OFF_X1 : OFF_X0);
        float d[2][8][4];
        #pragma unroll
        for (int mt = 0; mt < 2; mt++)
            #pragma unroll
            for (int nt = 0; nt < 8; nt++)
                #pragma unroll
                for (int j = 0; j < 4; j++) d[mt][nt][j] = 0.f;

        const uint32_t abase = xb + a_rel;
        #pragma unroll 4
        for (int ks = 0; ks < 16; ks++) {
            uint32_t a0[4], a1[4];
            ldsm_x4(a0[0], a0[1], a0[2], a0[3], abase + ks * 32);
            ldsm_x4(a1[0], a1[1], a1[2], a1[3], abase + 16 * WST * 2 + ks * 32);
            #pragma unroll
            for (int np = 0; np < 4; np++) {
                uint32_t b0, b1, b2, b3;
                ldsm_x4(b0, b1, b2, b3, b_base + (uint32_t)(np * 16 * WST) * 2 + ks * 32);
                mma16816(d[0][2 * np],     a0[0], a0[1], a0[2], a0[3], b0, b1);
                mma16816(d[0][2 * np + 1], a0[0], a0[1], a0[2], a0[3], b2, b3);
                mma16816(d[1][2 * np],     a1[0], a1[1], a1[2], a1[3], b0, b1);
                mma16816(d[1][2 * np + 1], a1[0], a1[1], a1[2], a1[3], b2, b3);
            }
        }

        // epilogue: tanh + Wv dot, per-warp 64-col partial -> g_attn_part[cg]
        {
            const float* h2 = g_hid2 + bb * Hd;
            float p[4] = {0.f, 0.f, 0.f, 0.f};
            #pragma unroll
            for (int nt = 0; nt < 8; nt++) {
                int col = c0 + nt * 8 + (lane & 3) * 2;
                float w0 = wv2s[col], w1 = wv2s[col + 1];
                float h0 = __ldg(h2 + col), h1 = __ldg(h2 + col + 1);
                #pragma unroll
                for (int mt = 0; mt < 2; mt++) {
                    p[mt * 2 + 0] += w0 * tanh_ap(fmaf(0.5f, d[mt][nt][0], h0))
                                   + w1 * tanh_ap(fmaf(0.5f, d[mt][nt][1], h1));
                    p[mt * 2 + 1] += w0 * tanh_ap(fmaf(0.5f, d[mt][nt][2], h0))
                                   + w1 * tanh_ap(fmaf(0.5f, d[mt][nt][3], h1));
                }
            }
            #pragma unroll
            for (int j = 0; j < 4; j++) {
                p[j] += __shfl_xor_sync(0xffffffffu, p[j], 1);
                p[j] += __shfl_xor_sync(0xffffffffu, p[j], 2);
            }
            if ((lane & 3) == 0) {
                int q = lane >> 2;
                size_t base = (size_t)cg * (Bd * Sd) + (size_t)bb * Sd + s0 + r0 + q;
                g_attn_part[base]      = p[0];
                g_attn_part[base + 8]  = p[1];
                g_attn_part[base + 16] = p[2];
                g_attn_part[base + 24] = p[3];
            }
        }
        __syncthreads();   // all warps done reading buf[i&1]; it may be refilled
    }
}

// ---------------- softmax over s, per b (sums 4 partial slices) -----------
__global__ void softmax_kernel(float* __restrict__ attn) {
    int b = blockIdx.x, tid = threadIdx.x;
    const size_t sl = (size_t)Bd * Sd;
    float* row = attn + b * Sd;
    float v[8]; float mx = -1e30f;
    #pragma unroll
    for (int t = 0; t < 8; t++) {
        size_t idx = (size_t)b * Sd + tid + 256 * t;
        v[t] = g_attn_part[idx] + g_attn_part[sl + idx]
             + g_attn_part[2 * sl + idx] + g_attn_part[3 * sl + idx];
        mx = fmaxf(mx, v[t]);
    }
    __shared__ float redm[8]; __shared__ float reds[8];
    #pragma unroll
    for (int o = 16; o; o >>= 1) mx = fmaxf(mx, __shfl_xor_sync(0xffffffffu, mx, o));
    if ((tid & 31) == 0) redm[tid >> 5] = mx;
    __syncthreads();
    mx = redm[0];
    #pragma unroll
    for (int i = 1; i < 8; i++) mx = fmaxf(mx, redm[i]);
    float sum = 0.f;
    #pragma unroll
    for (int t = 0; t < 8; t++) { v[t] = __expf(v[t] - mx); sum += v[t]; }
    #pragma unroll
    for (int o = 16; o; o >>= 1) sum += __shfl_xor_sync(0xffffffffu, sum, o);
    if ((tid & 31) == 0) reds[tid >> 5] = sum;
    __syncthreads();
    sum = 0.f;
    #pragma unroll
    for (int i = 0; i < 8; i++) sum += reds[i];
    float inv = 1.f / sum;
    #pragma unroll
    for (int t = 0; t < 8; t++) row[tid + 256 * t] = v[t] * inv;
}

// ---------------- context partials: stream fp32 encoder_outputs -----------
__global__ void ctx_part_kernel(const float* __restrict__ enc,
                                const float* __restrict__ attn) {
    int b = blockIdx.x, sc = blockIdx.y, h = threadIdx.x;
    int s0 = sc * 256;
    const float* wrow = attn + b * Sd + s0;
    const float* e = enc + ((size_t)s0 * Bd + b) * Hd + h;
    float a0 = 0.f, a1 = 0.f, a2 = 0.f, a3 = 0.f;
    #pragma unroll 2
    for (int s = 0; s < 256; s += 4) {
        a0 += wrow[s + 0] * e[(size_t)(s + 0) * (Bd * Hd)];
        a1 += wrow[s + 1] * e[(size_t)(s + 1) * (Bd * Hd)];
        a2 += wrow[s + 2] * e[(size_t)(s + 2) * (Bd * Hd)];
        a3 += wrow[s + 3] * e[(size_t)(s + 3) * (Bd * Hd)];
    }
    g_ctx_part[(sc * Bd + b) * Hd + h] = (a0 + a1) + (a2 + a3);
}

__global__ void ctx_reduce_kernel(float* __restrict__ out_ctx) {
    int b = blockIdx.x, h = threadIdx.x;
    float acc = 0.f;
    #pragma unroll
    for (int sc = 0; sc < 8; sc++) acc += g_ctx_part[(sc * Bd + b) * Hd + h];
    out_ctx[b * Hd + h] = acc;
}

// ---------------- GRU: weight-stationary gate GEMM ------------------------
__global__ __launch_bounds__(256)
void gru_gemm_kernel(const float* __restrict__ last_palette,
                     const float* __restrict__ ldh, const float* __restrict__ ctx,
                     const float* __restrict__ W_ih, const float* __restrict__ W_hh) {
    __shared__ float Wi[8][260];
    __shared__ float Whh[8][256];
    const int tid = threadIdx.x, lane = tid & 31, warp = tid >> 5;
    const int k0 = blockIdx.x * 8;
    const int KX = Hd + Pd;   // 259
    for (int idx = tid; idx < 8 * KX; idx += 256)
        Wi[idx / KX][idx % KX] = W_ih[(size_t)(k0 + idx / KX) * KX + idx % KX];
    for (int idx = tid; idx < 8 * Hd; idx += 256)
        Whh[idx >> 8][idx & 255] = W_hh[(size_t)(k0 + (idx >> 8)) * Hd + (idx & 255)];
    __syncthreads();

    for (int it = 0; it < 32; it++) {
        int b = warp + 8 * it;
        float xr[8], hr[8];
        #pragma unroll
        for (int t = 0; t < 8; t++) {
            int j = lane + 32 * t;
            xr[t] = (j < 3) ? last_palette[b * Pd + j] : ctx[b * Hd + (j - 3)];
            hr[t] = ldh[b * Hd + j];
        }
        float xe = (lane < 3) ? ctx[b * Hd + 253 + lane] : 0.f;
        #pragma unroll
        for (int o = 0; o < 8; o++) {
            float a = (lane < 3) ? xe * Wi[o][256 + lane] : 0.f;
            float c = 0.f;
            #pragma unroll
            for (int t = 0; t < 8; t++) {
                a += xr[t] * Wi[o][lane + 32 * t];
                c += hr[t] * Whh[o][lane + 32 * t];
            }
            #pragma unroll
            for (int off = 16; off; off >>= 1) {
                a += __shfl_xor_sync(0xffffffffu, a, off);
                c += __shfl_xor_sync(0xffffffffu, c, off);
            }
            if (lane == 0) {
                g_gi[(size_t)b * (3 * Hd) + k0 + o] = a;
                g_gh[(size_t)b * (3 * Hd) + k0 + o] = c;
            }
        }
    }
}

__global__ void gru_combine_kernel(const float* __restrict__ ldh,
                                   const float* __restrict__ b_ih,
                                   const float* __restrict__ b_hh,
                                   float* __restrict__ out_gru) {
    int b = blockIdx.x, k = threadIdx.x;
    const float* gi = g_gi + (size_t)b * (3 * Hd);
    const float* gh = g_gh + (size_t)b * (3 * Hd);
    float r = sigmoidf_(gi[k] + b_ih[k] + gh[k] + b_hh[k]);
    float z = sigmoidf_(gi[Hd + k] + b_ih[Hd + k] + gh[Hd + k] + b_hh[Hd + k]);
    float nn = tanhf(gi[2 * Hd + k] + b_ih[2 * Hd + k]
                     + r * (gh[2 * Hd + k] + b_hh[2 * Hd + k]));
    out_gru[b * Hd + k] = (1.f - z) * nn + z * ldh[b * Hd + k];
}

__global__ void h1_kernel(const float* __restrict__ gru, const float* __restrict__ W1,
                          const float* __restrict__ b1) {
    int b = blockIdx.x, tid = threadIdx.x, lane = tid & 31, warp = tid >> 5;
    __shared__ float gs[Hd];
    gs[tid] = gru[b * Hd + tid];
    __syncthreads();
    for (int k = warp; k < Hd; k += 8) {
        float a = 0.f;
        #pragma unroll
        for (int t = 0; t < 8; t++) a += gs[lane + 32 * t] * W1[k * Hd + lane + 32 * t];
        #pragma unroll
        for (int o = 16; o; o >>= 1) a += __shfl_xor_sync(0xffffffffu, a, o);
        if (lane == 0) g_h1[b * Hd + k] = fmaxf(a + b1[k], 0.f);
    }
}

// ---------------- BatchNorm stats, parallel (16 blocks) --------------------
__global__ void bn_kernel(const float* __restrict__ gamma, const float* __restrict__ beta) {
    __shared__ float ps[16][16];
    __shared__ float pq[16][16];
    int tid = threadIdx.x;
    int kl = tid & 15, bl = tid >> 4;
    int k = blockIdx.x * 16 + kl;
    float s = 0.f, sq = 0.f;
    #pragma unroll
    for (int j = 0; j < 16; j++) {
        float v = g_h1[(bl + 16 * j) * Hd + k];
        s += v; sq += v * v;
    }
    ps[bl][kl] = s; pq[bl][kl] = sq;
    __syncthreads();
    if (tid < 16) {
        float ts = 0.f, tq = 0.f;
        #pragma unroll
        for (int j = 0; j < 16; j++) { ts += ps[j][tid]; tq += pq[j][tid]; }
        int kk = blockIdx.x * 16 + tid;
        float mu = ts * (1.f / Bd);
        float var = tq * (1.f / Bd) - mu * mu;
        float sc = rsqrtf(var + 1e-5f) * gamma[kk];
        g_scale[kk] = sc; g_shift[kk] = beta[kk] - mu * sc;
    }
}

__global__ void palette_kernel(const float* __restrict__ W2, const float* __restrict__ b2,
                               float* __restrict__ out_pal) {
    int b = blockIdx.x, lane = threadIdx.x & 31, p = threadIdx.x >> 5;
    if (p >= Pd) return;
    float a = 0.f;
    #pragma unroll
    for (int t = 0; t < 8; t++) {
        int h = lane + 32 * t;
        a += (g_h1[b * Hd + h] * g_scale[h] + g_shift[h]) * W2[p * Hd + h];
    }
    #pragma unroll
    for (int o = 16; o; o >>= 1) a += __shfl_xor_sync(0xffffffffu, a, o);
    if (lane == 0) out_pal[b * Pd + p] = a + b2[p];
}

extern "C" void kernel_launch(void* const* d_in, const int* in_sizes, int n_in,
                              void* d_out, int out_size) {
    const float* last_palette = (const float*)d_in[0];
    const float* ldh          = (const float*)d_in[1];
    const float* enc          = (const float*)d_in[2];
    const float* We           = (const float*)d_in[3];
    const float* be           = (const float*)d_in[4];
    const float* Wh           = (const float*)d_in[5];
    const float* bh           = (const float*)d_in[6];
    const float* Wv           = (const float*)d_in[7];
    const float* W_ih         = (const float*)d_in[9];
    const float* b_ih         = (const float*)d_in[10];
    const float* W_hh         = (const float*)d_in[11];
    const float* b_hh         = (const float*)d_in[12];
    const float* W1           = (const float*)d_in[13];
    const float* b1           = (const float*)d_in[14];
    const float* gamma        = (const float*)d_in[15];
    const float* beta         = (const float*)d_in[16];
    const float* W2           = (const float*)d_in[17];
    const float* b2           = (const float*)d_in[18];

    float* out      = (float*)d_out;
    float* out_pal  = out;
    float* out_ctx  = out + Bd * Pd;
    float* out_gru  = out + Bd * Pd + Bd * Hd;
    float* out_attn = out + Bd * Pd + 2 * Bd * Hd;

    static bool attr_done = false;
    if (!attr_done) {
        cudaFuncSetAttribute(energy_hmma_kernel,
                             cudaFuncAttributeMaxDynamicSharedMemorySize, ESMEM);
        attr_done = true;
    }

    convert_kernel<<<Sd, 256>>>(enc);
    hid2_kernel<<<Bd, 256>>>(ldh, Wh, bh, be);
    energy_hmma_kernel<<<NCTAS, 256, ESMEM>>>(We, Wv);
    softmax_kernel<<<Bd, 256>>>(out_attn);
    ctx_part_kernel<<<dim3(Bd, 8), 256>>>(enc, out_attn);
    ctx_reduce_kernel<<<Bd, 256>>>(out_ctx);
    gru_gemm_kernel<<<96, 256>>>(last_palette, ldh, out_ctx, W_ih, W_hh);
    gru_combine_kernel<<<Bd, 256>>>(ldh, b_ih, b_hh, out_gru);
    h1_kernel<<<Bd, 256>>>(out_gru, W1, b1);
    bn_kernel<<<16, 256>>>(gamma, beta);
    palette_kernel<<<Bd, 128>>>(W2, b2, out_pal);
}